// round 6
// baseline (speedup 1.0000x reference)
#include <cuda_runtime.h>

#define NPIX   (480*480)
#define NCLS   124
#define FCH    64
#define IN_HW  120
#define EPS_F  1e-8f
#define GRID   444        // 148 SMs x 3 co-resident blocks (regs<=85)
#define SETUP0 240        // setup blocks [240, 364)
#define BIN0   364        // bin blocks  [364, 444)
#define NBIN   80
#define BINPX  2880       // 80*2880 = 230400 exactly

// ---------------- device scratch (zero at first entry; restored each run) ----
__device__ __align__(16) float g_feats_t[IN_HW*IN_HW*FCH];   // [y][x][c]
__device__ __align__(16) float g_mn[NCLS*FCH];
__device__ float g_iszero[NCLS];
__device__ int   g_hist[NCLS];          // counts (reset in finalize)
__device__ int   g_cursor[NCLS];        // reservation cursors (reset in finalize)
__device__ int   g_binned[NPIX];        // pix | (cls<<18), class-contiguous
__device__ __align__(16) float g_sum[NCLS*FCH];
__device__ __align__(16) float g_wx[NCLS*FCH];
__device__ float g_wsum[NCLS];

__device__ int      g_bar_count = 0;    // self-resetting
__device__ unsigned g_bar_gen   = 0;    // monotonic across replays

__constant__ float c_frac[4] = {0.625f, 0.875f, 0.125f, 0.375f};

// Grid barrier: RED arrive, block 0 polls + flips generation.
// SCAN=true: block 0 does the 124-class exclusive scan inside the critical
// section (block 0 is a transpose block, so its 'h' scratch is free here).
template<bool SCAN>
__device__ __forceinline__ void gsync(int* h) {
    const int t = threadIdx.x;
    __syncthreads();
    __threadfence();
    unsigned my = 0;
    if (t == 0) {
        my = *(volatile unsigned*)&g_bar_gen;
        atomicAdd(&g_bar_count, 1);              // return unused -> RED
    }
    if (blockIdx.x == 0) {
        if (t == 0) {
            while (*(volatile int*)&g_bar_count < GRID) __nanosleep(32);
            __threadfence();
        }
        __syncthreads();
        if (SCAN) {
            int hv = 0;
            if (t < 128) { hv = (t < NCLS) ? g_hist[t] : 0; h[t] = hv; }
            __syncthreads();
            #pragma unroll
            for (int o = 1; o < 128; o <<= 1) {
                int u = (t < 128 && t >= o) ? h[t - o] : 0;
                __syncthreads();
                if (t < 128) h[t] += u;
                __syncthreads();
            }
            if (t < NCLS) g_cursor[t] = h[t] - hv;   // exclusive prefix
        }
        __threadfence();
        __syncthreads();
        if (t == 0) {
            g_bar_count = 0;
            __threadfence();
            *(volatile unsigned*)&g_bar_gen = my + 1;
        }
    } else {
        if (t == 0) {
            while (*(volatile unsigned*)&g_bar_gen == my) __nanosleep(32);
            __threadfence();
        }
    }
    __syncthreads();
}

__global__ void __launch_bounds__(256, 3)
k_mega(const float* __restrict__ feats, const float* __restrict__ memory,
       const int* __restrict__ seg, float* __restrict__ out) {
    __shared__ float tile[FCH*61];   // 15616B: transpose half-row (60 cols, pad 61)
    __shared__ int   h[128];         // bin hist/bases; block0: scan scratch
    const int b = blockIdx.x;
    const int t = threadIdx.x;

    // ---- phase 0: transpose(240) | setup(124) | per-block histogram(80) ----
    if (b < SETUP0) {
        const int y  = b >> 1;
        const int xh = (b & 1) * 60;
        for (int i = t; i < FCH*60; i += 256) {
            int c = i / 60, x = i - c*60;
            tile[c*61 + x] = feats[c*IN_HW*IN_HW + y*IN_HW + xh + x];
        }
        __syncthreads();
        for (int i = t; i < 60*FCH; i += 256) {
            int x = i >> 6, c = i & 63;
            g_feats_t[(y*IN_HW + xh + x)*FCH + c] = tile[c*61 + x];
        }
    } else if (b < BIN0) {
        const int c = b - SETUP0;
        if (t < 32) {                    // warp 0: normalize memory row
            float v0 = memory[c*FCH + t];
            float v1 = memory[c*FCH + t + 32];
            float s = v0*v0 + v1*v1;
            #pragma unroll
            for (int o = 16; o; o >>= 1) s += __shfl_xor_sync(0xffffffffu, s, o);
            float inv = 1.0f / fmaxf(sqrtf(s), EPS_F);
            g_mn[c*FCH + t]      = v0 * inv;
            g_mn[c*FCH + t + 32] = v1 * inv;
            if (t == 0) {
                g_iszero[c] = (s == 0.0f) ? 1.0f : 0.0f;
                g_wsum[c] = 0.0f;
            }
        } else if (t < 96) {             // disjoint threads: zero accumulators
            g_sum[c*FCH + (t - 32)] = 0.0f;
            g_wx [c*FCH + (t - 32)] = 0.0f;
        }
    } else {
        if (t < 128) h[t] = 0;
        __syncthreads();
        const int base = (b - BIN0) * BINPX;
        for (int i = t; i < BINPX; i += 256)
            atomicAdd(&h[seg[base + i]], 1);
        __syncthreads();
        if (t < NCLS && h[t]) atomicAdd(&g_hist[t], h[t]);   // RED (no return)
    }
    gsync<true>(h);     // barrier + class scan (g_cursor = exclusive prefix)

    // ---- phase 1: scatter (bin blocks reserve ranges, fill via smem cursors)
    if (b >= BIN0) {
        if (t < NCLS) {
            int cnt = h[t];
            h[t] = cnt ? atomicAdd(&g_cursor[t], cnt) : 0;   // block's base
        }
        __syncthreads();
        const int base = (b - BIN0) * BINPX;
        for (int i = t; i < BINPX; i += 256) {
            int pix = base + i;
            int c = seg[pix];
            int slot = atomicAdd(&h[c], 1);                  // smem cursor
            g_binned[slot] = pix | (c << 18);
        }
    }
    gsync<false>(h);

    // ---- phase 2: main (8 lanes/pixel, 4 pixels/warp-iter, packed prefetch) --
    {
        const int lane = t & 31;
        const int sub  = lane >> 3;
        const int sl   = lane & 7;
        const int gw   = (b*256 + t) >> 5;
        const int nw   = (GRID*256) >> 5;
        const int chunk = (NPIX + nw - 1) / nw;
        const int j0   = gw * chunk;
        const int jend = min(j0 + chunk, NPIX);

        if (j0 < jend) {
            const float4* __restrict__ ft4 = (const float4*)g_feats_t;
            const float4* __restrict__ mn4 = (const float4*)g_mn;

            float4 sA = {0,0,0,0}, sB = {0,0,0,0}, wA = {0,0,0,0}, wB = {0,0,0,0};
            float  aw = 0.f;
            float4 mA = {0,0,0,0}, mB = {0,0,0,0};
            int cur = -1;

            int packed = g_binned[min(j0 + sub, jend - 1)];  // pipeline prologue

            for (int j = j0; j < jend; j += 4) {
                // prefetch next iteration's packed (clamped, branchless)
                const int packed_next =
                    g_binned[min(min(j + 4 + sub, jend - 1), NPIX - 1)];

                const bool valid = (j + sub) < jend;
                const int cls = packed >> 18;
                const int pix = packed & 0x3FFFF;

                const int oy = pix / 480;
                const int ox = pix - oy*480;
                const int iy0 = (oy >> 2) + ((oy >> 1) & 1) - 1;
                const int ix0 = (ox >> 2) + ((ox >> 1) & 1) - 1;
                const float fy = c_frac[oy & 3];
                const float fx = c_frac[ox & 3];
                const int y0 = max(iy0, 0), y1 = min(iy0 + 1, IN_HW - 1);
                const int x0 = max(ix0, 0), x1 = min(ix0 + 1, IN_HW - 1);
                const float w11 = fy * fx;
                const float w10 = fy - w11;
                const float w01 = fx - w11;
                const float w00 = 1.0f - fy - fx + w11;

                const int rA = (y0*IN_HW + x0)*16, rB = (y0*IN_HW + x1)*16;
                const int rC = (y1*IN_HW + x0)*16, rD = (y1*IN_HW + x1)*16;
                const float4 a0 = ft4[rA + sl],     b0 = ft4[rB + sl];
                const float4 c0 = ft4[rC + sl],     d0 = ft4[rD + sl];
                const float4 a1 = ft4[rA + 8 + sl], b1 = ft4[rB + 8 + sl];
                const float4 c1 = ft4[rC + 8 + sl], d1 = ft4[rD + 8 + sl];

                if (__any_sync(0xffffffffu, cls != cur)) {
                    if (cls != cur) {
                        if (cur >= 0) {
                            atomicAdd((float4*)&g_sum[cur*FCH + 4*sl],      sA);
                            atomicAdd((float4*)&g_sum[cur*FCH + 32 + 4*sl], sB);
                            atomicAdd((float4*)&g_wx [cur*FCH + 4*sl],      wA);
                            atomicAdd((float4*)&g_wx [cur*FCH + 32 + 4*sl], wB);
                            if (sl == 0) atomicAdd(&g_wsum[cur], aw);
                        }
                        sA = make_float4(0,0,0,0); sB = make_float4(0,0,0,0);
                        wA = make_float4(0,0,0,0); wB = make_float4(0,0,0,0);
                        aw = 0.f;
                        cur = cls;
                        mA = mn4[cls*16 + sl];
                        mB = mn4[cls*16 + 8 + sl];
                    }
                }

                float4 v0, v1;
                v0.x = w00*a0.x + w01*b0.x + w10*c0.x + w11*d0.x;
                v0.y = w00*a0.y + w01*b0.y + w10*c0.y + w11*d0.y;
                v0.z = w00*a0.z + w01*b0.z + w10*c0.z + w11*d0.z;
                v0.w = w00*a0.w + w01*b0.w + w10*c0.w + w11*d0.w;
                v1.x = w00*a1.x + w01*b1.x + w10*c1.x + w11*d1.x;
                v1.y = w00*a1.y + w01*b1.y + w10*c1.y + w11*d1.y;
                v1.z = w00*a1.z + w01*b1.z + w10*c1.z + w11*d1.z;
                v1.w = w00*a1.w + w01*b1.w + w10*c1.w + w11*d1.w;

                float nsq = v0.x*v0.x + v0.y*v0.y + v0.z*v0.z + v0.w*v0.w
                          + v1.x*v1.x + v1.y*v1.y + v1.z*v1.z + v1.w*v1.w;
                float dt  = v0.x*mA.x + v0.y*mA.y + v0.z*mA.z + v0.w*mA.w
                          + v1.x*mB.x + v1.y*mB.y + v1.z*mB.z + v1.w*mB.w;
                #pragma unroll
                for (int o = 4; o; o >>= 1) {
                    nsq += __shfl_xor_sync(0xffffffffu, nsq, o);
                    dt  += __shfl_xor_sync(0xffffffffu, dt,  o);
                }
                const float wgt = 1.0f - dt * rsqrtf(fmaxf(nsq, 1e-16f));
                const float vv = valid ? 1.0f : 0.0f;
                const float g  = valid ? wgt : 0.0f;

                sA.x = fmaf(vv, v0.x, sA.x); sA.y = fmaf(vv, v0.y, sA.y);
                sA.z = fmaf(vv, v0.z, sA.z); sA.w = fmaf(vv, v0.w, sA.w);
                sB.x = fmaf(vv, v1.x, sB.x); sB.y = fmaf(vv, v1.y, sB.y);
                sB.z = fmaf(vv, v1.z, sB.z); sB.w = fmaf(vv, v1.w, sB.w);
                wA.x = fmaf(g, v0.x, wA.x);  wA.y = fmaf(g, v0.y, wA.y);
                wA.z = fmaf(g, v0.z, wA.z);  wA.w = fmaf(g, v0.w, wA.w);
                wB.x = fmaf(g, v1.x, wB.x);  wB.y = fmaf(g, v1.y, wB.y);
                wB.z = fmaf(g, v1.z, wB.z);  wB.w = fmaf(g, v1.w, wB.w);
                aw += g;

                packed = packed_next;
            }

            if (cur >= 0) {
                atomicAdd((float4*)&g_sum[cur*FCH + 4*sl],      sA);
                atomicAdd((float4*)&g_sum[cur*FCH + 32 + 4*sl], sB);
                atomicAdd((float4*)&g_wx [cur*FCH + 4*sl],      wA);
                atomicAdd((float4*)&g_wx [cur*FCH + 32 + 4*sl], wB);
                if (sl == 0) atomicAdd(&g_wsum[cur], aw);
            }
        }
    }
    gsync<false>(h);

    // ---- phase 3: finalize + restore scratch for next replay ----
    if (b < NCLS) {
        const int c = b;
        if (t < FCH) {
            const int cnt = g_hist[c];
            const float memv = memory[c*FCH + t];
            float res = memv;
            if (cnt > 0) {
                if (g_iszero[c] != 0.0f) {
                    res = g_sum[c*FCH + t] / fmaxf((float)cnt, 1.0f);
                } else {
                    const float ws = g_wsum[c];
                    const float weighted = g_wx[c*FCH + t] / ((ws != 0.0f) ? ws : 1.0f);
                    res = 0.9f * memv + 0.1f * weighted;
                }
            }
            out[c*FCH + t] = res;
        }
        __syncthreads();
        if (t == 0) { g_hist[c] = 0; g_cursor[c] = 0; }
    }
}

// ---------------- launch ----------------
extern "C" void kernel_launch(void* const* d_in, const int* in_sizes, int n_in,
                              void* d_out, int out_size) {
    const float* feats  = (const float*)d_in[0];
    const float* memory = (const float*)d_in[1];
    const int*   seg    = (const int*)  d_in[2];
    float* out = (float*)d_out;
    k_mega<<<GRID, 256>>>(feats, memory, seg, out);
}

// round 7
// speedup vs baseline: 1.4012x; 1.4012x over previous
#include <cuda_runtime.h>

#define NPIX   (480*480)
#define NCLS   124
#define FCH    64
#define IN_HW  120
#define EPS_F  1e-8f
#define GRID   444        // 148 SMs x 3 co-resident blocks (regs<=85)
#define SETUP0 240        // setup blocks [240, 364)
#define BIN0   364        // bin blocks  [364, 444)
#define NBIN   80
#define BINPX  2880       // 80*2880 = 230400 exactly

// ---------------- device scratch (zero at first entry; restored each run) ----
__device__ __align__(16) float g_feats_t[IN_HW*IN_HW*FCH];   // [y][x][c]
__device__ __align__(16) float g_mn[NCLS*FCH];
__device__ float g_iszero[NCLS];
__device__ int   g_hist[NCLS];          // counts (reset in finalize)
__device__ int   g_cursor[NCLS];        // reservation cursors (reset in finalize)
__device__ int   g_binned[NPIX];        // pix | (cls<<18), class-contiguous
__device__ __align__(16) float g_sum[NCLS*FCH];
__device__ __align__(16) float g_wx[NCLS*FCH];
__device__ float g_wsum[NCLS];

__device__ int      g_bar_count = 0;    // self-resetting
__device__ unsigned g_bar_gen   = 0;    // monotonic across replays

__constant__ float c_frac[4] = {0.625f, 0.875f, 0.125f, 0.375f};

// Grid barrier: RED arrive, block 0 polls + flips generation.
// SCAN=true: block 0 does the 124-class exclusive scan inside the critical
// section (block 0 is a transpose block, so its 'h' scratch is free here).
template<bool SCAN>
__device__ __forceinline__ void gsync(int* h) {
    const int t = threadIdx.x;
    __syncthreads();
    __threadfence();
    unsigned my = 0;
    if (t == 0) {
        my = *(volatile unsigned*)&g_bar_gen;
        atomicAdd(&g_bar_count, 1);              // return unused -> RED
    }
    if (blockIdx.x == 0) {
        if (t == 0) {
            while (*(volatile int*)&g_bar_count < GRID) __nanosleep(32);
            __threadfence();
        }
        __syncthreads();
        if (SCAN) {
            int hv = 0;
            if (t < 128) { hv = (t < NCLS) ? g_hist[t] : 0; h[t] = hv; }
            __syncthreads();
            #pragma unroll
            for (int o = 1; o < 128; o <<= 1) {
                int u = (t < 128 && t >= o) ? h[t - o] : 0;
                __syncthreads();
                if (t < 128) h[t] += u;
                __syncthreads();
            }
            if (t < NCLS) g_cursor[t] = h[t] - hv;   // exclusive prefix
        }
        __threadfence();
        __syncthreads();
        if (t == 0) {
            g_bar_count = 0;
            __threadfence();
            *(volatile unsigned*)&g_bar_gen = my + 1;
        }
    } else {
        if (t == 0) {
            while (*(volatile unsigned*)&g_bar_gen == my) __nanosleep(32);
            __threadfence();
        }
    }
    __syncthreads();
}

__global__ void __launch_bounds__(256, 3)
k_mega(const float* __restrict__ feats, const float* __restrict__ memory,
       const int* __restrict__ seg, float* __restrict__ out) {
    __shared__ float tile[FCH*61];   // 15616B: transpose half-row (60 cols, pad 61)
    __shared__ int   h[128];         // bin hist/bases; block0: scan scratch
    const int b = blockIdx.x;
    const int t = threadIdx.x;

    // ---- phase 0: transpose(240) | setup(124) | per-block histogram(80) ----
    if (b < SETUP0) {
        const int y  = b >> 1;
        const int xh = (b & 1) * 60;
        for (int i = t; i < FCH*60; i += 256) {
            int c = i / 60, x = i - c*60;
            tile[c*61 + x] = feats[c*IN_HW*IN_HW + y*IN_HW + xh + x];
        }
        __syncthreads();
        for (int i = t; i < 60*FCH; i += 256) {
            int x = i >> 6, c = i & 63;
            g_feats_t[(y*IN_HW + xh + x)*FCH + c] = tile[c*61 + x];
        }
    } else if (b < BIN0) {
        const int c = b - SETUP0;
        if (t < 32) {                    // warp 0: normalize memory row
            float v0 = memory[c*FCH + t];
            float v1 = memory[c*FCH + t + 32];
            float s = v0*v0 + v1*v1;
            #pragma unroll
            for (int o = 16; o; o >>= 1) s += __shfl_xor_sync(0xffffffffu, s, o);
            float inv = 1.0f / fmaxf(sqrtf(s), EPS_F);
            g_mn[c*FCH + t]      = v0 * inv;
            g_mn[c*FCH + t + 32] = v1 * inv;
            if (t == 0) {
                g_iszero[c] = (s == 0.0f) ? 1.0f : 0.0f;
                g_wsum[c] = 0.0f;
            }
        } else if (t < 96) {             // disjoint threads: zero accumulators
            g_sum[c*FCH + (t - 32)] = 0.0f;
            g_wx [c*FCH + (t - 32)] = 0.0f;
        }
    } else {
        if (t < 128) h[t] = 0;
        __syncthreads();
        const int base = (b - BIN0) * BINPX;
        for (int i = t; i < BINPX; i += 256)
            atomicAdd(&h[seg[base + i]], 1);
        __syncthreads();
        if (t < NCLS && h[t]) atomicAdd(&g_hist[t], h[t]);   // RED (no return)
    }
    gsync<true>(h);     // barrier + class scan (g_cursor = exclusive prefix)

    // ---- phase 1: scatter (bin blocks reserve ranges, fill via smem cursors)
    if (b >= BIN0) {
        if (t < NCLS) {
            int cnt = h[t];
            h[t] = cnt ? atomicAdd(&g_cursor[t], cnt) : 0;   // block's base
        }
        __syncthreads();
        const int base = (b - BIN0) * BINPX;
        for (int i = t; i < BINPX; i += 256) {
            int pix = base + i;
            int c = seg[pix];
            int slot = atomicAdd(&h[c], 1);                  // smem cursor
            g_binned[slot] = pix | (c << 18);
        }
    }
    gsync<false>(h);

    // ---- phase 2: main (8 lanes/pixel, 4 pixels/warp-iter) ----
    // NOTE: exact Round-5 loop body (no packed prefetch) — the prefetch
    // variant inflated dynamic instruction count ~70% and regressed 15us.
    {
        const int lane = t & 31;
        const int sub  = lane >> 3;
        const int sl   = lane & 7;
        const int gw   = (b*256 + t) >> 5;
        const int nw   = (GRID*256) >> 5;
        const int chunk = (NPIX + nw - 1) / nw;
        const int j0   = gw * chunk;
        const int jend = min(j0 + chunk, NPIX);

        if (j0 < jend) {
            const float4* __restrict__ ft4 = (const float4*)g_feats_t;
            const float4* __restrict__ mn4 = (const float4*)g_mn;

            float4 sA = {0,0,0,0}, sB = {0,0,0,0}, wA = {0,0,0,0}, wB = {0,0,0,0};
            float  aw = 0.f;
            float4 mA = {0,0,0,0}, mB = {0,0,0,0};
            int cur = -1;

            for (int j = j0; j < jend; j += 4) {
                const int idx    = j + sub;
                const bool valid = idx < jend;
                const int packed = g_binned[valid ? idx : (jend - 1)];
                const int cls = packed >> 18;
                const int pix = packed & 0x3FFFF;

                const int oy = pix / 480;
                const int ox = pix - oy*480;
                const int iy0 = (oy >> 2) + ((oy >> 1) & 1) - 1;
                const int ix0 = (ox >> 2) + ((ox >> 1) & 1) - 1;
                const float fy = c_frac[oy & 3];
                const float fx = c_frac[ox & 3];
                const int y0 = max(iy0, 0), y1 = min(iy0 + 1, IN_HW - 1);
                const int x0 = max(ix0, 0), x1 = min(ix0 + 1, IN_HW - 1);
                const float w11 = fy * fx;
                const float w10 = fy - w11;
                const float w01 = fx - w11;
                const float w00 = 1.0f - fy - fx + w11;

                const int rA = (y0*IN_HW + x0)*16, rB = (y0*IN_HW + x1)*16;
                const int rC = (y1*IN_HW + x0)*16, rD = (y1*IN_HW + x1)*16;
                const float4 a0 = ft4[rA + sl],     b0 = ft4[rB + sl];
                const float4 c0 = ft4[rC + sl],     d0 = ft4[rD + sl];
                const float4 a1 = ft4[rA + 8 + sl], b1 = ft4[rB + 8 + sl];
                const float4 c1 = ft4[rC + 8 + sl], d1 = ft4[rD + 8 + sl];

                if (__any_sync(0xffffffffu, cls != cur)) {
                    if (cls != cur) {
                        if (cur >= 0) {
                            atomicAdd((float4*)&g_sum[cur*FCH + 4*sl],      sA);
                            atomicAdd((float4*)&g_sum[cur*FCH + 32 + 4*sl], sB);
                            atomicAdd((float4*)&g_wx [cur*FCH + 4*sl],      wA);
                            atomicAdd((float4*)&g_wx [cur*FCH + 32 + 4*sl], wB);
                            if (sl == 0) atomicAdd(&g_wsum[cur], aw);
                        }
                        sA = make_float4(0,0,0,0); sB = make_float4(0,0,0,0);
                        wA = make_float4(0,0,0,0); wB = make_float4(0,0,0,0);
                        aw = 0.f;
                        cur = cls;
                        mA = mn4[cls*16 + sl];
                        mB = mn4[cls*16 + 8 + sl];
                    }
                }

                float4 v0, v1;
                v0.x = w00*a0.x + w01*b0.x + w10*c0.x + w11*d0.x;
                v0.y = w00*a0.y + w01*b0.y + w10*c0.y + w11*d0.y;
                v0.z = w00*a0.z + w01*b0.z + w10*c0.z + w11*d0.z;
                v0.w = w00*a0.w + w01*b0.w + w10*c0.w + w11*d0.w;
                v1.x = w00*a1.x + w01*b1.x + w10*c1.x + w11*d1.x;
                v1.y = w00*a1.y + w01*b1.y + w10*c1.y + w11*d1.y;
                v1.z = w00*a1.z + w01*b1.z + w10*c1.z + w11*d1.z;
                v1.w = w00*a1.w + w01*b1.w + w10*c1.w + w11*d1.w;

                float nsq = v0.x*v0.x + v0.y*v0.y + v0.z*v0.z + v0.w*v0.w
                          + v1.x*v1.x + v1.y*v1.y + v1.z*v1.z + v1.w*v1.w;
                float dt  = v0.x*mA.x + v0.y*mA.y + v0.z*mA.z + v0.w*mA.w
                          + v1.x*mB.x + v1.y*mB.y + v1.z*mB.z + v1.w*mB.w;
                #pragma unroll
                for (int o = 4; o; o >>= 1) {
                    nsq += __shfl_xor_sync(0xffffffffu, nsq, o);
                    dt  += __shfl_xor_sync(0xffffffffu, dt,  o);
                }
                const float wgt = 1.0f - dt * rsqrtf(fmaxf(nsq, 1e-16f));
                const float vv = valid ? 1.0f : 0.0f;
                const float g  = valid ? wgt : 0.0f;

                sA.x = fmaf(vv, v0.x, sA.x); sA.y = fmaf(vv, v0.y, sA.y);
                sA.z = fmaf(vv, v0.z, sA.z); sA.w = fmaf(vv, v0.w, sA.w);
                sB.x = fmaf(vv, v1.x, sB.x); sB.y = fmaf(vv, v1.y, sB.y);
                sB.z = fmaf(vv, v1.z, sB.z); sB.w = fmaf(vv, v1.w, sB.w);
                wA.x = fmaf(g, v0.x, wA.x);  wA.y = fmaf(g, v0.y, wA.y);
                wA.z = fmaf(g, v0.z, wA.z);  wA.w = fmaf(g, v0.w, wA.w);
                wB.x = fmaf(g, v1.x, wB.x);  wB.y = fmaf(g, v1.y, wB.y);
                wB.z = fmaf(g, v1.z, wB.z);  wB.w = fmaf(g, v1.w, wB.w);
                aw += g;
            }

            if (cur >= 0) {
                atomicAdd((float4*)&g_sum[cur*FCH + 4*sl],      sA);
                atomicAdd((float4*)&g_sum[cur*FCH + 32 + 4*sl], sB);
                atomicAdd((float4*)&g_wx [cur*FCH + 4*sl],      wA);
                atomicAdd((float4*)&g_wx [cur*FCH + 32 + 4*sl], wB);
                if (sl == 0) atomicAdd(&g_wsum[cur], aw);
            }
        }
    }
    gsync<false>(h);

    // ---- phase 3: finalize + restore scratch for next replay ----
    if (b < NCLS) {
        const int c = b;
        if (t < FCH) {
            const int cnt = g_hist[c];
            const float memv = memory[c*FCH + t];
            float res = memv;
            if (cnt > 0) {
                if (g_iszero[c] != 0.0f) {
                    res = g_sum[c*FCH + t] / fmaxf((float)cnt, 1.0f);
                } else {
                    const float ws = g_wsum[c];
                    const float weighted = g_wx[c*FCH + t] / ((ws != 0.0f) ? ws : 1.0f);
                    res = 0.9f * memv + 0.1f * weighted;
                }
            }
            out[c*FCH + t] = res;
        }
        __syncthreads();
        if (t == 0) { g_hist[c] = 0; g_cursor[c] = 0; }
    }
}

// ---------------- launch ----------------
extern "C" void kernel_launch(void* const* d_in, const int* in_sizes, int n_in,
                              void* d_out, int out_size) {
    const float* feats  = (const float*)d_in[0];
    const float* memory = (const float*)d_in[1];
    const int*   seg    = (const int*)  d_in[2];
    float* out = (float*)d_out;
    k_mega<<<GRID, 256>>>(feats, memory, seg, out);
}